// round 15
// baseline (speedup 1.0000x reference)
#include <cuda_runtime.h>
#include <math.h>
#include <stdint.h>

#define BATCH 2048
#define DIN   512
#define DOUT  512
#define DINT  512
#define DNL   256

#define BAT_BLOCKS  168
#define GJ_BLOCKS   120
#define TOT_BLOCKS  288

#define MEGA_SMEM 67584

// ---------------- device scratch ----------------
__device__ __align__(16) float g_WLU[512 * 1024];
__device__ __align__(16) float g_Dinvall[8][64 * 64];  // per-step pivot inverses
__device__ __align__(16) float g_a[BATCH * DNL];
__device__ __align__(16) float g_wm[BATCH * DNL];
__device__ __align__(16) float g_D11T[DNL * DNL];
__device__ __align__(16) float g_W1[DOUT * DNL];
__device__ __align__(16) float g_W2[DOUT * DIN];
__device__ __align__(16) float g_c1x0[DNL];
__device__ __align__(16) float g_fx0[DINT];
__device__ __align__(16) float g_ybias[DOUT];
__device__ int g_prog[16 * 8];        // steps completed per (column j, chunk c)
__device__ int g_colc[16];            // per-column completion count
__device__ int g_commitflag[16];
__device__ int g_commitc;
__device__ volatile int g_dgen;
__device__ volatile int g_bar_gj;
__device__ volatile int g_bar_bat;
__device__ volatile int g_done;
__device__ volatile int g_prep;
__device__ volatile int g_recdone;
__device__ int g_yctr;

__global__ void reset_kernel() {
    int t = threadIdx.x;
    if (t < 128) g_prog[t] = 0;
    if (t < 16) { g_colc[t] = 0; g_commitflag[t] = 0; }
    if (t == 0) {
        g_commitc = 0; g_dgen = -1;
        g_bar_gj = 0; g_bar_bat = 0; g_done = 0; g_prep = 0; g_recdone = 0;
        g_yctr = 0;
    }
}

// ---------------- group barrier ----------------
__device__ __forceinline__ void gbar(volatile int* ctr, int nblocks, int& phase, int tid) {
    __threadfence();
    __syncthreads();
    ++phase;
    if (tid == 0) {
        atomicAdd((int*)ctr, 1);
        const int target = nblocks * phase;
        while (*ctr < target) __nanosleep(128);
        __threadfence();
    }
    __syncthreads();
}

__device__ __forceinline__ void wait_flag(volatile int* flag, int tid) {
    if (tid == 0) {
        while (*flag == 0) __nanosleep(128);
        __threadfence();
    }
    __syncthreads();
}

// ---------------- fully-unrolled 64x64 GJ inversion core ----------------
__device__ __forceinline__ void gj_inv_core(int tid, float v[4][8],
                                            float* rowbuf, float* colbuf,
                                            float* __restrict__ outg) {
    const int rg = tid >> 4, cg = tid & 15;
#pragma unroll 64
    for (int jj = 0; jj < 64; ++jj) {
        const int pr = jj >> 2, sub = jj & 3;
        const int pcg = jj >> 3, subc = jj & 7;
        if (rg == pr) {
#pragma unroll
            for (int q = 0; q < 8; ++q) rowbuf[cg * 8 + q] = v[sub][q];
        }
        if (cg == pcg) {
#pragma unroll
            for (int i = 0; i < 4; ++i) colbuf[rg * 4 + i] = v[i][subc];
        }
        __syncthreads();
        const float pinv = 1.0f / rowbuf[jj];
        float f[4];
#pragma unroll
        for (int i = 0; i < 4; ++i) f[i] = colbuf[rg * 4 + i] * pinv;
        float rv[8];
#pragma unroll
        for (int q = 0; q < 8; ++q) rv[q] = rowbuf[cg * 8 + q];
        if (rg == pr) {
#pragma unroll
            for (int q = 0; q < 8; ++q) v[sub][q] = rv[q] * pinv;
        }
#pragma unroll
        for (int i = 0; i < 4; ++i) {
            if (rg == pr && i == sub) continue;
#pragma unroll
            for (int q = 0; q < 8; ++q) v[i][q] -= f[i] * rv[q];
        }
        __syncthreads();
    }
#pragma unroll
    for (int i = 0; i < 4; ++i) {
        int r = (tid >> 4) * 4 + i;
#pragma unroll
        for (int jx = 0; jx < 8; ++jx) {
            int cx = (tid & 15) * 8 + jx;
            if (cx >= 64) outg[r * 64 + (cx - 64)] = v[i][jx];
        }
    }
    __syncthreads();
}

__device__ __forceinline__ void invert_from_gwlu(int pc, int tid,
                                                 float* rowbuf, float* colbuf,
                                                 float* outg) {
    const int rg = tid >> 4, cg = tid & 15;
    float v[4][8];
#pragma unroll
    for (int i = 0; i < 4; ++i) {
        int r = rg * 4 + i;
#pragma unroll
        for (int jx = 0; jx < 8; ++jx) {
            int cx = cg * 8 + jx;
            v[i][jx] = (cx < 64) ? g_WLU[(size_t)(pc + r) * 1024 + pc + cx]
                                 : ((cx - 64) == r ? 1.f : 0.f);
        }
    }
    gj_inv_core(tid, v, rowbuf, colbuf, outg);
}

__device__ __forceinline__ void invert_from_sh(const float* Ts, int tid,
                                               float* rowbuf, float* colbuf,
                                               float* outg) {
    const int rg = tid >> 4, cg = tid & 15;
    float v[4][8];
#pragma unroll
    for (int i = 0; i < 4; ++i) {
        int r = rg * 4 + i;
#pragma unroll
        for (int jx = 0; jx < 8; ++jx) {
            int cx = cg * 8 + jx;
            v[i][jx] = (cx < 64) ? Ts[r * 65 + cx] : ((cx - 64) == r ? 1.f : 0.f);
        }
    }
    gj_inv_core(tid, v, rowbuf, colbuf, outg);
}

// ---------------- TN tile ----------------
__device__ void tn_tile(float* __restrict__ C,
                        const float* __restrict__ A, int lda,
                        const float* __restrict__ B, int ldb,
                        const float* __restrict__ Add, int N, int K,
                        int m0, int n0, int tid, float* smem) {
    float* As = smem;
    float* Bs = smem + 16 * 68;
    const int tr = tid >> 4, tc = tid & 15;
    float acc[4][4] = {};
    for (int t0 = 0; t0 < K; t0 += 16) {
        __syncthreads();
        for (int idx = tid; idx < 1024; idx += 256) {
            int t = idx >> 6, m = idx & 63;
            As[t * 68 + m] = A[(size_t)(t0 + t) * lda + m0 + m];
            Bs[t * 68 + m] = B[(size_t)(t0 + t) * ldb + n0 + m];
        }
        __syncthreads();
#pragma unroll
        for (int t = 0; t < 16; ++t) {
            float a[4], bv[4];
#pragma unroll
            for (int i = 0; i < 4; ++i) a[i] = As[t * 68 + tr * 4 + i];
#pragma unroll
            for (int jx = 0; jx < 4; ++jx) bv[jx] = Bs[t * 68 + tc * 4 + jx];
#pragma unroll
            for (int i = 0; i < 4; ++i)
#pragma unroll
                for (int jx = 0; jx < 4; ++jx) acc[i][jx] += a[i] * bv[jx];
        }
    }
    __syncthreads();
#pragma unroll
    for (int i = 0; i < 4; ++i) {
        int r = m0 + tr * 4 + i;
#pragma unroll
        for (int jx = 0; jx < 4; ++jx) {
            float v = acc[i][jx];
            if (Add) v += Add[(size_t)r * N + n0 + tc * 4 + jx];
            C[(size_t)r * N + n0 + tc * 4 + jx] = v;
        }
    }
}

// ---------------- 3xTF32 MMA GEMM machinery ----------------
__device__ __forceinline__ uint32_t f2tf(float f) {
    uint32_t u;
    asm("cvt.rna.tf32.f32 %0, %1;" : "=r"(u) : "f"(f));
    return u;
}
__device__ __forceinline__ void mma8(float& c0, float& c1, float& c2, float& c3,
                                     uint32_t a0, uint32_t a1, uint32_t a2, uint32_t a3,
                                     uint32_t b0, uint32_t b1) {
    asm volatile(
        "mma.sync.aligned.m16n8k8.row.col.f32.tf32.tf32.f32 "
        "{%0,%1,%2,%3},{%4,%5,%6,%7},{%8,%9},{%0,%1,%2,%3};"
        : "+f"(c0), "+f"(c1), "+f"(c2), "+f"(c3)
        : "r"(a0), "r"(a1), "r"(a2), "r"(a3), "r"(b0), "r"(b1));
}

#define ASTRIDE 20
#define ABUF (128 * ASTRIDE)
#define BBUF (64 * ASTRIDE)

__device__ __forceinline__ void stage_store(uint32_t* Ah, uint32_t* Al,
                                            uint32_t* Bh, uint32_t* Bl,
                                            int arow, int akq, int brow, int bkq,
                                            float4 ra0, float4 ra1, float4 rb0) {
    uint32_t* ah = Ah + arow * ASTRIDE + akq;
    uint32_t* al = Al + arow * ASTRIDE + akq;
    float av[8] = {ra0.x, ra0.y, ra0.z, ra0.w, ra1.x, ra1.y, ra1.z, ra1.w};
#pragma unroll
    for (int jx = 0; jx < 8; ++jx) {
        uint32_t h = f2tf(av[jx]);
        ah[jx] = h;
        al[jx] = f2tf(av[jx] - __uint_as_float(h));
    }
    uint32_t* bh = Bh + brow * ASTRIDE + bkq;
    uint32_t* bl = Bl + brow * ASTRIDE + bkq;
    float bv[4] = {rb0.x, rb0.y, rb0.z, rb0.w};
#pragma unroll
    for (int jx = 0; jx < 4; ++jx) {
        uint32_t h = f2tf(bv[jx]);
        bh[jx] = h;
        bl[jx] = f2tf(bv[jx] - __uint_as_float(h));
    }
}

__device__ void gemm_part(const float* __restrict__ A,
                          const float* __restrict__ Bm,
                          int K, int ldb, int m0, int n0, int tid,
                          uint32_t* Ah, uint32_t* Al,
                          uint32_t* Bh, uint32_t* Bl,
                          float (&acc)[2][4][4]) {
    const int arow = tid >> 1, akq = (tid & 1) * 8;
    const int brow = tid >> 2, bkq = (tid & 3) * 4;
    const int lane = tid & 31, warp = tid >> 5;
    const int wm = warp >> 1, wn = warp & 1, g = lane >> 2, tg = lane & 3;
    const int nt = K >> 4;
    float4 ra0, ra1, rb0;
    {
        const float* ap = A + (size_t)(m0 + arow) * K + akq;
        ra0 = *(const float4*)ap;
        ra1 = *(const float4*)(ap + 4);
        const float* bp = Bm + (size_t)(n0 + brow) * ldb + bkq;
        rb0 = *(const float4*)bp;
    }
    __syncthreads();
    stage_store(Ah, Al, Bh, Bl, arow, akq, brow, bkq, ra0, ra1, rb0);
    __syncthreads();
    for (int t = 0; t < nt; ++t) {
        const int c = t & 1;
        if (t + 1 < nt) {
            const float* ap = A + (size_t)(m0 + arow) * K + (t + 1) * 16 + akq;
            ra0 = *(const float4*)ap;
            ra1 = *(const float4*)(ap + 4);
            const float* bp = Bm + (size_t)(n0 + brow) * ldb + (t + 1) * 16 + bkq;
            rb0 = *(const float4*)bp;
        }
        const uint32_t* Abh = Ah + c * ABUF;
        const uint32_t* Abl = Al + c * ABUF;
        const uint32_t* Bbh = Bh + c * BBUF;
        const uint32_t* Bbl = Bl + c * BBUF;
#pragma unroll
        for (int ks = 0; ks < 16; ks += 8) {
            uint32_t ah[2][4], al[2][4], bh[4][2], bl[4][2];
#pragma unroll
            for (int i = 0; i < 2; ++i) {
                int r = (wm * 32 + i * 16 + g) * ASTRIDE + ks + tg;
                ah[i][0] = Abh[r];                   al[i][0] = Abl[r];
                ah[i][1] = Abh[r + 8 * ASTRIDE];     al[i][1] = Abl[r + 8 * ASTRIDE];
                ah[i][2] = Abh[r + 4];               al[i][2] = Abl[r + 4];
                ah[i][3] = Abh[r + 8 * ASTRIDE + 4]; al[i][3] = Abl[r + 8 * ASTRIDE + 4];
            }
#pragma unroll
            for (int jx = 0; jx < 4; ++jx) {
                int r = (wn * 32 + jx * 8 + g) * ASTRIDE + ks + tg;
                bh[jx][0] = Bbh[r];     bl[jx][0] = Bbl[r];
                bh[jx][1] = Bbh[r + 4]; bl[jx][1] = Bbl[r + 4];
            }
#pragma unroll
            for (int i = 0; i < 2; ++i)
#pragma unroll
                for (int jx = 0; jx < 4; ++jx) {
                    mma8(acc[i][jx][0], acc[i][jx][1], acc[i][jx][2], acc[i][jx][3],
                         al[i][0], al[i][1], al[i][2], al[i][3], bh[jx][0], bh[jx][1]);
                    mma8(acc[i][jx][0], acc[i][jx][1], acc[i][jx][2], acc[i][jx][3],
                         ah[i][0], ah[i][1], ah[i][2], ah[i][3], bl[jx][0], bl[jx][1]);
                    mma8(acc[i][jx][0], acc[i][jx][1], acc[i][jx][2], acc[i][jx][3],
                         ah[i][0], ah[i][1], ah[i][2], ah[i][3], bh[jx][0], bh[jx][1]);
                }
        }
        __syncthreads();
        if (t + 1 < nt) {
            stage_store(Ah + (1 - c) * ABUF, Al + (1 - c) * ABUF,
                        Bh + (1 - c) * BBUF, Bl + (1 - c) * BBUF,
                        arow, akq, brow, bkq, ra0, ra1, rb0);
            __syncthreads();
        }
    }
}

__device__ void gemm_tile(float* __restrict__ C, int N, const float* __restrict__ bias,
                          const float* A0, const float* B0, int K0, int l0,
                          const float* A1, const float* B1, int K1, int l1,
                          int m0, int n0, int tid, uint32_t* sm_u) {
    uint32_t* Ah = sm_u;
    uint32_t* Bh = Ah + 2 * ABUF;
    uint32_t* Al = Bh + 2 * BBUF;
    uint32_t* Bl = Al + 2 * ABUF;
    float acc[2][4][4];
#pragma unroll
    for (int i = 0; i < 2; ++i)
#pragma unroll
        for (int jx = 0; jx < 4; ++jx)
#pragma unroll
            for (int q = 0; q < 4; ++q) acc[i][jx][q] = 0.f;

    gemm_part(A0, B0, K0, l0, m0, n0, tid, Ah, Al, Bh, Bl, acc);
    if (A1) gemm_part(A1, B1, K1, l1, m0, n0, tid, Ah, Al, Bh, Bl, acc);

    const int lane = tid & 31, warp = tid >> 5;
    const int wm = warp >> 1, wn = warp & 1, g = lane >> 2, tg = lane & 3;
#pragma unroll
    for (int i = 0; i < 2; ++i)
#pragma unroll
        for (int jx = 0; jx < 4; ++jx) {
            int r = m0 + wm * 32 + i * 16 + g;
            int cc = n0 + wn * 32 + jx * 8 + 2 * tg;
            float2 bb = make_float2(0.f, 0.f);
            if (bias) bb = *(const float2*)&bias[cc];
            *(float2*)&C[(size_t)r * N + cc] =
                make_float2(acc[i][jx][0] + bb.x, acc[i][jx][1] + bb.y);
            *(float2*)&C[(size_t)(r + 8) * N + cc] =
                make_float2(acc[i][jx][2] + bb.x, acc[i][jx][3] + bb.y);
        }
}

// =====================================================================
// MEGA KERNEL v6: dataflow-pipelined GJ (no per-step group barriers)
// =====================================================================
__global__ void __launch_bounds__(256, 2) mega_kernel(
    const float* __restrict__ u, const float* __restrict__ x0,
    const float* __restrict__ C1, const float* __restrict__ D11,
    const float* __restrict__ D12, const float* __restrict__ lam,
    const float* __restrict__ Fm, const float* __restrict__ B1,
    const float* __restrict__ B2, const float* __restrict__ E,
    const float* __restrict__ C2, const float* __restrict__ D22,
    float* __restrict__ yout) {
    extern __shared__ float smf[];
    __shared__ int s_tile;
    const int b = blockIdx.x;
    const int tid = threadIdx.x;
    int phase = 0;

    if (b >= BAT_BLOCKS) {
        // ================= GJ GROUP (120 blocks) =================
        const int g = b - BAT_BLOCKS;          // 0..119
        const int j = 1 + (g >> 3);            // column block 1..15 (cols j*64..)
        const int cch = g & 7;                 // row chunk 0..7
        const int L = (j < 8) ? j : 8;         // number of steps for this column
        float* Ds = smf;                       // 64x65
        float* RP = Ds + 64 * 65;
        float* Fs = RP + 64 * 65;
        float* Cs = Fs + 64 * 65;              // deferred chunk save
        float* rowbuf = Cs + 64 * 65;          // 128
        float* colbuf = rowbuf + 128;          // 64
        const int tr = tid >> 4, tc = tid & 15;
        const int c0 = j * 64;

        // --- transposed init: WLU = [E^T | C2^T] ---
        {
            float* tsh = smf;
            const int tx = tid & 31, ty = tid >> 5;
            for (int tu = g; tu < 512; tu += GJ_BLOCKS) {
                const int R0 = (tu & 15) * 32;
                const int Cc0 = (tu >> 4) * 32;
                const float* src = (Cc0 < 512) ? (E + (size_t)Cc0 * 512 + R0)
                                               : (C2 + (size_t)(Cc0 - 512) * 512 + R0);
                __syncthreads();
#pragma unroll
                for (int i = 0; i < 32; i += 8)
                    tsh[(ty + i) * 33 + tx] = src[(size_t)(ty + i) * 512 + tx];
                __syncthreads();
#pragma unroll
                for (int i = 0; i < 32; i += 8)
                    g_WLU[(size_t)(R0 + ty + i) * 1024 + Cc0 + tx] = tsh[tx * 33 + ty + i];
            }
        }
        gbar(&g_bar_gj, GJ_BLOCKS, phase, tid);

        // --- bootstrap: block 119 inverts pivot(0) ---
        if (g == 119) {
            invert_from_gwlu(0, tid, rowbuf, colbuf, &g_Dinvall[0][0]);
            __threadfence();
            if (tid == 0) g_dgen = 0;
        }

        // --- pipelined steps ---
        for (int kb = 0; kb < L; ++kb) {
            // dependency waits (monotonic counters)
            if (tid == 0) {
                while (g_dgen < kb) __nanosleep(64);
                if (cch != kb)
                    while (*(volatile int*)&g_prog[j * 8 + kb] < kb) __nanosleep(64);
                if (kb >= 1) {
                    if (cch == kb - 1) {
                        while (*(volatile int*)&g_commitflag[kb] == 0) __nanosleep(64);
                    } else {
                        while (*(volatile int*)&g_prog[kb * 8 + cch] < kb) __nanosleep(64);
                    }
                }
            }
            __syncthreads();
            __threadfence();

            const int pc = kb * 64;
            // load Dinv(kb)
            const float* dsrc = &g_Dinvall[kb][0];
            for (int idx = tid; idx < 4096; idx += 256)
                Ds[(idx >> 6) * 65 + (idx & 63)] = dsrc[idx];
            // Wk = W[pivot rows kb][col j]
            for (int idx = tid; idx < 4096; idx += 256) {
                int k = idx >> 6, cx = idx & 63;
                Fs[k * 65 + cx] = g_WLU[(size_t)(pc + k) * 1024 + c0 + cx];
            }
            __syncthreads();

            // RP = Dinv @ Wk
            float rp[4][4] = {};
            for (int k = 0; k < 64; ++k) {
                float w0 = Fs[k * 65 + tc * 4 + 0];
                float w1 = Fs[k * 65 + tc * 4 + 1];
                float w2 = Fs[k * 65 + tc * 4 + 2];
                float w3 = Fs[k * 65 + tc * 4 + 3];
#pragma unroll
                for (int i = 0; i < 4; ++i) {
                    float d = Ds[(tr * 4 + i) * 65 + k];
                    rp[i][0] += d * w0; rp[i][1] += d * w1;
                    rp[i][2] += d * w2; rp[i][3] += d * w3;
                }
            }
            __syncthreads();
#pragma unroll
            for (int i = 0; i < 4; ++i)
#pragma unroll
                for (int jx = 0; jx < 4; ++jx)
                    RP[(tr * 4 + i) * 65 + tc * 4 + jx] = rp[i][jx];
            __syncthreads();

            if (cch == kb) {
                // defer: save RP as my chunk's new value; DON'T write W yet
                for (int idx = tid; idx < 4096; idx += 256) {
                    int r = idx >> 6, cx = idx & 63;
                    Cs[r * 65 + cx] = RP[r * 65 + cx];
                }
                __syncthreads();
            } else {
                const int r0 = cch * 64;
                const bool fromCs = (kb == cch + 1);  // deferred at previous step
                // F = W[rows cch][pivot col kb] (final values)
                for (int idx = tid; idx < 4096; idx += 256) {
                    int r = idx >> 6, k = idx & 63;
                    Fs[r * 65 + k] = g_WLU[(size_t)(r0 + r) * 1024 + pc + k];
                }
                __syncthreads();
                float acc[4][4] = {};
                for (int k = 0; k < 64; ++k) {
                    float w0 = RP[k * 65 + tc * 4 + 0];
                    float w1 = RP[k * 65 + tc * 4 + 1];
                    float w2 = RP[k * 65 + tc * 4 + 2];
                    float w3 = RP[k * 65 + tc * 4 + 3];
#pragma unroll
                    for (int i = 0; i < 4; ++i) {
                        float f = Fs[(tr * 4 + i) * 65 + k];
                        acc[i][0] += f * w0; acc[i][1] += f * w1;
                        acc[i][2] += f * w2; acc[i][3] += f * w3;
                    }
                }
                float nv[4][4];
#pragma unroll
                for (int i = 0; i < 4; ++i) {
                    const size_t off = (size_t)(r0 + tr * 4 + i) * 1024 + c0 + tc * 4;
                    float4 o;
                    if (fromCs) {
                        o.x = Cs[(tr * 4 + i) * 65 + tc * 4 + 0];
                        o.y = Cs[(tr * 4 + i) * 65 + tc * 4 + 1];
                        o.z = Cs[(tr * 4 + i) * 65 + tc * 4 + 2];
                        o.w = Cs[(tr * 4 + i) * 65 + tc * 4 + 3];
                    } else {
                        o = *(const float4*)&g_WLU[off];
                    }
                    o.x -= acc[i][0]; o.y -= acc[i][1];
                    o.z -= acc[i][2]; o.w -= acc[i][3];
                    nv[i][0] = o.x; nv[i][1] = o.y; nv[i][2] = o.z; nv[i][3] = o.w;
                    *(float4*)&g_WLU[off] = o;
                }
                // designee (j,j) at final step: new chunk IS pivot(j) -> invert+publish
                if (cch == j && kb == L - 1 && j <= 7) {
                    __syncthreads();  // F reads of Fs done
#pragma unroll
                    for (int i = 0; i < 4; ++i)
#pragma unroll
                        for (int jx = 0; jx < 4; ++jx)
                            Fs[(tr * 4 + i) * 65 + tc * 4 + jx] = nv[i][jx];
                    __syncthreads();
                    invert_from_sh(Fs, tid, rowbuf, colbuf, &g_Dinvall[j][0]);
                    __threadfence();
                    if (tid == 0) g_dgen = j;
                }
            }
            // publish progress
            __threadfence();
            __syncthreads();
            if (tid == 0) *(volatile int*)&g_prog[j * 8 + cch] = kb + 1;
        }

        // column completion arrival
        __threadfence();
        __syncthreads();
        if (tid == 0) atomicAdd(&g_colc[j], 1);

        // committer: deferred-at-final-step chunk (cch == L-1)
        if (cch == L - 1) {
            if (tid == 0) {
                while (*(volatile int*)&g_colc[j] < 8) __nanosleep(64);
                __threadfence();
            }
            __syncthreads();
            const int r0 = (L - 1) * 64;
            for (int idx = tid; idx < 4096; idx += 256) {
                int r = idx >> 6, cx = idx & 63;
                g_WLU[(size_t)(r0 + r) * 1024 + c0 + cx] = Cs[r * 65 + cx];
            }
            __threadfence();
            __syncthreads();
            if (tid == 0) {
                *(volatile int*)&g_commitflag[j] = 1;
                atomicAdd(&g_commitc, 1);
            }
        }

        // wait for ALL columns final (G complete)
        if (tid == 0) {
            while (*(volatile int*)&g_commitc < 15) __nanosleep(128);
            __threadfence();
        }
        __syncthreads();

        // --- fold: W1 (32), W2 (64), ybias (2) = 98 units, one per block ---
        const float* G = &g_WLU[512];
        if (g < 98) {
            int fu = g;
            if (fu < 32) {
                tn_tile(g_W1, G, 1024, B1, 256, nullptr, 256, 512,
                        (fu >> 2) * 64, (fu & 3) * 64, tid, smf);
            } else if (fu < 96) {
                int q = fu - 32;
                tn_tile(g_W2, G, 1024, B2, 512, D22, 512, 512,
                        (q >> 3) * 64, (q & 7) * 64, tid, smf);
            } else {
                wait_flag(&g_prep, tid);
                float* xs = smf;
                for (int i = tid; i < 512; i += 256) xs[i] = g_fx0[i];
                __syncthreads();
                int n = (fu - 96) * 256 + tid;
                float sv = 0.f;
#pragma unroll 8
                for (int t = 0; t < 512; ++t) sv += G[(size_t)t * 1024 + n] * xs[t];
                g_ybias[n] = sv;
                __syncthreads();
            }
        }
        gbar(&g_bar_gj, GJ_BLOCKS, phase, tid);
        if (g == 0 && tid == 0) {
            __threadfence();
            atomicExch((int*)&g_done, 1);
        }

        wait_flag(&g_recdone, tid);
    } else {
        // ================= BATCH GROUP (168 blocks) =================
        const int v = b;

        if (v < 67) {
            if (v < 64) {
                float* tsh = smf;
                const int bx = (v & 7) * 32, by = (v >> 3) * 32;
                const int tx = tid & 31, ty = tid >> 5;
#pragma unroll
                for (int i = 0; i < 32; i += 8)
                    tsh[(ty + i) * 33 + tx] = D11[(size_t)(by + ty + i) * 256 + bx + tx];
                __syncthreads();
#pragma unroll
                for (int i = 0; i < 32; i += 8)
                    g_D11T[(size_t)(bx + ty + i) * 256 + by + tx] = tsh[tx * 33 + ty + i];
            } else {
                const float4* xv = (const float4*)x0;
                if (v == 64) {
                    int n = tid;
                    const float4* r = (const float4*)(C1 + (size_t)n * DIN);
                    float s = 0.f;
                    for (int k = 0; k < DIN / 4; ++k) {
                        float4 a = r[k], bb = xv[k];
                        s += a.x * bb.x + a.y * bb.y + a.z * bb.z + a.w * bb.w;
                    }
                    g_c1x0[n] = s;
                } else {
                    int n = (v - 65) * 256 + tid;
                    const float4* r = (const float4*)(Fm + (size_t)n * DINT);
                    float s = 0.f;
                    for (int k = 0; k < DINT / 4; ++k) {
                        float4 a = r[k], bb = xv[k];
                        s += a.x * bb.x + a.y * bb.y + a.z * bb.z + a.w * bb.w;
                    }
                    g_fx0[n] = s;
                }
            }
        }
        gbar(&g_bar_bat, BAT_BLOCKS, phase, tid);
        if (v == 0 && tid == 0) {
            __threadfence();
            atomicExch((int*)&g_prep, 1);
        }

        if (v < 64) {
            gemm_tile(g_a, 256, g_c1x0,
                      u, D12, 512, 512,
                      nullptr, nullptr, 0, 0,
                      (v >> 2) * 128, (v & 3) * 64, tid, (uint32_t*)smf);
        }
        gbar(&g_bar_bat, BAT_BLOCKS, phase, tid);

        for (int ru = v; ru < 256; ru += BAT_BLOCKS) {
            const int lane = tid & 31;
            const int rb = ru * 8 + (tid >> 5);
            const float* arow = g_a + (size_t)rb * 256;
            float acc[8], linv[8], wv[8];
#pragma unroll
            for (int q = 0; q < 8; ++q) {
                acc[q] = arow[q * 32 + lane];
                linv[q] = 1.0f / lam[q * 32 + lane];
            }
#pragma unroll
            for (int q = 0; q < 8; ++q) {
#pragma unroll 8
                for (int t = 0; t < 32; ++t) {
                    int s = q * 32 + t;
                    float scaled = acc[q] * linv[q];
                    float vx = __shfl_sync(0xffffffffu, scaled, t);
                    float wt = tanhf(vx);
                    if (lane == t) wv[q] = wt;
                    const float* col = g_D11T + (size_t)s * 256;
                    if (lane > t) acc[q] += col[q * 32 + lane] * wt;
#pragma unroll
                    for (int q2 = q + 1; q2 < 8; ++q2)
                        acc[q2] += col[q2 * 32 + lane] * wt;
                }
            }
#pragma unroll
            for (int q = 0; q < 8; ++q)
                g_wm[(size_t)rb * 256 + q * 32 + lane] = wv[q];
        }
        gbar(&g_bar_bat, BAT_BLOCKS, phase, tid);
        if (v == 0 && tid == 0) {
            __threadfence();
            atomicExch((int*)&g_recdone, 1);
        }

        wait_flag(&g_done, tid);
    }

    // ============ shared y-GEMM work queue (all 288 blocks) ============
    for (;;) {
        __syncthreads();
        if (tid == 0) s_tile = atomicAdd(&g_yctr, 1);
        __syncthreads();
        const int t = s_tile;
        if (t >= 128) break;
        gemm_tile(yout, 512, g_ybias,
                  g_wm, g_W1, 256, 256,
                  u, g_W2, 512, 512,
                  (t >> 3) * 128, (t & 7) * 64, tid, (uint32_t*)smf);
    }
}

// ---------------- launch ----------------
extern "C" void kernel_launch(void* const* d_in, const int* in_sizes, int n_in,
                              void* d_out, int out_size) {
    const float *u, *x0, *C1, *D11, *D12, *lam, *Fm, *B1, *B2, *E, *C2, *D21, *D22;
    if (in_sizes[0] == BATCH * DIN) {
        u   = (const float*)d_in[0];  x0  = (const float*)d_in[1];
        C1  = (const float*)d_in[2];  D11 = (const float*)d_in[3];
        D12 = (const float*)d_in[4];  lam = (const float*)d_in[5];
        Fm  = (const float*)d_in[6];  B1  = (const float*)d_in[7];
        B2  = (const float*)d_in[8];  E   = (const float*)d_in[9];
        C2  = (const float*)d_in[10]; D21 = (const float*)d_in[11];
        D22 = (const float*)d_in[12];
    } else {
        C1  = (const float*)d_in[0];  D11 = (const float*)d_in[1];
        D12 = (const float*)d_in[2];  lam = (const float*)d_in[3];
        Fm  = (const float*)d_in[4];  B1  = (const float*)d_in[5];
        B2  = (const float*)d_in[6];  E   = (const float*)d_in[7];
        C2  = (const float*)d_in[8];  D21 = (const float*)d_in[9];
        D22 = (const float*)d_in[10]; u   = (const float*)d_in[11];
        x0  = (const float*)d_in[12];
    }
    (void)D21;  // identically zero by construction

    cudaFuncSetAttribute(mega_kernel,
                         cudaFuncAttributeMaxDynamicSharedMemorySize, MEGA_SMEM);

    reset_kernel<<<1, 128>>>();
    mega_kernel<<<TOT_BLOCKS, 256, MEGA_SMEM>>>(
        u, x0, C1, D11, D12, lam, Fm, B1, B2, E, C2, D22, (float*)d_out);
}

// round 16
// speedup vs baseline: 1.1552x; 1.1552x over previous
#include <cuda_runtime.h>
#include <math.h>
#include <stdint.h>

#define BATCH 2048
#define DIN   512
#define DOUT  512
#define DINT  512
#define DNL   256

#define BAT_BLOCKS  168
#define GJ_BLOCKS   120
#define TOT_BLOCKS  288

#define GEMM_SMEM ((2 * (128 * 20) + 2 * (64 * 20)) * 8)  // 61440

// ---------------- device scratch ----------------
__device__ __align__(16) float g_WLU[512 * 1024];
__device__ __align__(16) float g_RPbuf[2][64 * 1024];
__device__ __align__(16) float g_Dinvg[2][64 * 64];
__device__ __align__(16) float g_a[BATCH * DNL];
__device__ __align__(16) float g_wm[BATCH * DNL];
__device__ __align__(16) float g_z[BATCH * DINT];
__device__ __align__(16) float g_Mc[DOUT * DINT];   // M = C2 E^-1, row-major
__device__ __align__(16) float g_D11T[DNL * DNL];
__device__ __align__(16) float g_c1x0[DNL];
__device__ __align__(16) float g_fx0[DINT];
__device__ volatile int g_bar_gj;
__device__ volatile int g_bar_bat;
__device__ volatile int g_done;     // GJ: Mc ready
__device__ volatile int g_batdone;  // batch: z + yD ready
__device__ volatile int g_dgen;
__device__ int g_yctr;

__global__ void reset_kernel() {
    g_bar_gj = 0; g_bar_bat = 0; g_done = 0; g_batdone = 0;
    g_dgen = -1; g_yctr = 0;
}

// ---------------- sync helpers ----------------
__device__ __forceinline__ void gbar(volatile int* ctr, int nblocks, int& phase, int tid) {
    __syncthreads();
    ++phase;
    if (tid == 0) {
        __threadfence();
        atomicAdd((int*)ctr, 1);
        const int target = nblocks * phase;
        while (*ctr < target) __nanosleep(64);
        __threadfence();
    }
    __syncthreads();
}

__device__ __forceinline__ void wait_flag(volatile int* flag, int tid) {
    if (tid == 0) {
        while (*flag == 0) __nanosleep(128);
        __threadfence();
    }
    __syncthreads();
}

// ---------------- fully-unrolled 64x64 GJ inversion core ----------------
__device__ __forceinline__ void gj_inv_core(int tid, float v[4][8],
                                            float* rowbuf, float* colbuf,
                                            float* __restrict__ outg) {
    const int rg = tid >> 4, cg = tid & 15;
#pragma unroll 64
    for (int jj = 0; jj < 64; ++jj) {
        const int pr = jj >> 2, sub = jj & 3;
        const int pcg = jj >> 3, subc = jj & 7;
        if (rg == pr) {
#pragma unroll
            for (int q = 0; q < 8; ++q) rowbuf[cg * 8 + q] = v[sub][q];
        }
        if (cg == pcg) {
#pragma unroll
            for (int i = 0; i < 4; ++i) colbuf[rg * 4 + i] = v[i][subc];
        }
        __syncthreads();
        const float pinv = 1.0f / rowbuf[jj];
        float f[4];
#pragma unroll
        for (int i = 0; i < 4; ++i) f[i] = colbuf[rg * 4 + i] * pinv;
        float rv[8];
#pragma unroll
        for (int q = 0; q < 8; ++q) rv[q] = rowbuf[cg * 8 + q];
        if (rg == pr) {
#pragma unroll
            for (int q = 0; q < 8; ++q) v[sub][q] = rv[q] * pinv;
        }
#pragma unroll
        for (int i = 0; i < 4; ++i) {
            if (rg == pr && i == sub) continue;
#pragma unroll
            for (int q = 0; q < 8; ++q) v[i][q] -= f[i] * rv[q];
        }
        __syncthreads();
    }
#pragma unroll
    for (int i = 0; i < 4; ++i) {
        int r = (tid >> 4) * 4 + i;
#pragma unroll
        for (int jx = 0; jx < 8; ++jx) {
            int cx = (tid & 15) * 8 + jx;
            if (cx >= 64) outg[r * 64 + (cx - 64)] = v[i][jx];
        }
    }
    __syncthreads();
}

__device__ __forceinline__ void invert_from_gwlu(int pc, int tid,
                                                 float* rowbuf, float* colbuf,
                                                 float* outg) {
    const int rg = tid >> 4, cg = tid & 15;
    float v[4][8];
#pragma unroll
    for (int i = 0; i < 4; ++i) {
        int r = rg * 4 + i;
#pragma unroll
        for (int jx = 0; jx < 8; ++jx) {
            int cx = cg * 8 + jx;
            v[i][jx] = (cx < 64) ? g_WLU[(size_t)(pc + r) * 1024 + pc + cx]
                                 : ((cx - 64) == r ? 1.f : 0.f);
        }
    }
    gj_inv_core(tid, v, rowbuf, colbuf, outg);
}

__device__ __forceinline__ void invert_from_sh(const float* Ts, int tid,
                                               float* rowbuf, float* colbuf,
                                               float* outg) {
    const int rg = tid >> 4, cg = tid & 15;
    float v[4][8];
#pragma unroll
    for (int i = 0; i < 4; ++i) {
        int r = rg * 4 + i;
#pragma unroll
        for (int jx = 0; jx < 8; ++jx) {
            int cx = cg * 8 + jx;
            v[i][jx] = (cx < 64) ? Ts[r * 65 + cx] : ((cx - 64) == r ? 1.f : 0.f);
        }
    }
    gj_inv_core(tid, v, rowbuf, colbuf, outg);
}

// ---------------- 3xTF32 MMA GEMM machinery ----------------
__device__ __forceinline__ uint32_t f2tf(float f) {
    uint32_t u;
    asm("cvt.rna.tf32.f32 %0, %1;" : "=r"(u) : "f"(f));
    return u;
}
__device__ __forceinline__ void mma8(float& c0, float& c1, float& c2, float& c3,
                                     uint32_t a0, uint32_t a1, uint32_t a2, uint32_t a3,
                                     uint32_t b0, uint32_t b1) {
    asm volatile(
        "mma.sync.aligned.m16n8k8.row.col.f32.tf32.tf32.f32 "
        "{%0,%1,%2,%3},{%4,%5,%6,%7},{%8,%9},{%0,%1,%2,%3};"
        : "+f"(c0), "+f"(c1), "+f"(c2), "+f"(c3)
        : "r"(a0), "r"(a1), "r"(a2), "r"(a3), "r"(b0), "r"(b1));
}

#define ASTRIDE 20
#define ABUF (128 * ASTRIDE)
#define BBUF (64 * ASTRIDE)

__device__ __forceinline__ void stage_store(uint32_t* Ah, uint32_t* Al,
                                            uint32_t* Bh, uint32_t* Bl,
                                            int arow, int akq, int brow, int bkq,
                                            float4 ra0, float4 ra1, float4 rb0) {
    uint32_t* ah = Ah + arow * ASTRIDE + akq;
    uint32_t* al = Al + arow * ASTRIDE + akq;
    float av[8] = {ra0.x, ra0.y, ra0.z, ra0.w, ra1.x, ra1.y, ra1.z, ra1.w};
#pragma unroll
    for (int jx = 0; jx < 8; ++jx) {
        uint32_t h = f2tf(av[jx]);
        ah[jx] = h;
        al[jx] = f2tf(av[jx] - __uint_as_float(h));
    }
    uint32_t* bh = Bh + brow * ASTRIDE + bkq;
    uint32_t* bl = Bl + brow * ASTRIDE + bkq;
    float bv[4] = {rb0.x, rb0.y, rb0.z, rb0.w};
#pragma unroll
    for (int jx = 0; jx < 4; ++jx) {
        uint32_t h = f2tf(bv[jx]);
        bh[jx] = h;
        bl[jx] = f2tf(bv[jx] - __uint_as_float(h));
    }
}

__device__ void gemm_part(const float* __restrict__ A,
                          const float* __restrict__ Bm,
                          int K, int ldb, int m0, int n0, int tid,
                          uint32_t* Ah, uint32_t* Al,
                          uint32_t* Bh, uint32_t* Bl,
                          float (&acc)[2][4][4]) {
    const int arow = tid >> 1, akq = (tid & 1) * 8;
    const int brow = tid >> 2, bkq = (tid & 3) * 4;
    const int lane = tid & 31, warp = tid >> 5;
    const int wm = warp >> 1, wn = warp & 1, g = lane >> 2, tg = lane & 3;
    const int nt = K >> 4;
    float4 ra0, ra1, rb0;
    {
        const float* ap = A + (size_t)(m0 + arow) * K + akq;
        ra0 = *(const float4*)ap;
        ra1 = *(const float4*)(ap + 4);
        const float* bp = Bm + (size_t)(n0 + brow) * ldb + bkq;
        rb0 = *(const float4*)bp;
    }
    __syncthreads();
    stage_store(Ah, Al, Bh, Bl, arow, akq, brow, bkq, ra0, ra1, rb0);
    __syncthreads();
    for (int t = 0; t < nt; ++t) {
        const int c = t & 1;
        if (t + 1 < nt) {
            const float* ap = A + (size_t)(m0 + arow) * K + (t + 1) * 16 + akq;
            ra0 = *(const float4*)ap;
            ra1 = *(const float4*)(ap + 4);
            const float* bp = Bm + (size_t)(n0 + brow) * ldb + (t + 1) * 16 + bkq;
            rb0 = *(const float4*)bp;
        }
        const uint32_t* Abh = Ah + c * ABUF;
        const uint32_t* Abl = Al + c * ABUF;
        const uint32_t* Bbh = Bh + c * BBUF;
        const uint32_t* Bbl = Bl + c * BBUF;
#pragma unroll
        for (int ks = 0; ks < 16; ks += 8) {
            uint32_t ah[2][4], al[2][4], bh[4][2], bl[4][2];
#pragma unroll
            for (int i = 0; i < 2; ++i) {
                int r = (wm * 32 + i * 16 + g) * ASTRIDE + ks + tg;
                ah[i][0] = Abh[r];                   al[i][0] = Abl[r];
                ah[i][1] = Abh[r + 8 * ASTRIDE];     al[i][1] = Abl[r + 8 * ASTRIDE];
                ah[i][2] = Abh[r + 4];               al[i][2] = Abl[r + 4];
                ah[i][3] = Abh[r + 8 * ASTRIDE + 4]; al[i][3] = Abl[r + 8 * ASTRIDE + 4];
            }
#pragma unroll
            for (int jx = 0; jx < 4; ++jx) {
                int r = (wn * 32 + jx * 8 + g) * ASTRIDE + ks + tg;
                bh[jx][0] = Bbh[r];     bl[jx][0] = Bbl[r];
                bh[jx][1] = Bbh[r + 4]; bl[jx][1] = Bbl[r + 4];
            }
#pragma unroll
            for (int i = 0; i < 2; ++i)
#pragma unroll
                for (int jx = 0; jx < 4; ++jx) {
                    mma8(acc[i][jx][0], acc[i][jx][1], acc[i][jx][2], acc[i][jx][3],
                         al[i][0], al[i][1], al[i][2], al[i][3], bh[jx][0], bh[jx][1]);
                    mma8(acc[i][jx][0], acc[i][jx][1], acc[i][jx][2], acc[i][jx][3],
                         ah[i][0], ah[i][1], ah[i][2], ah[i][3], bl[jx][0], bl[jx][1]);
                    mma8(acc[i][jx][0], acc[i][jx][1], acc[i][jx][2], acc[i][jx][3],
                         ah[i][0], ah[i][1], ah[i][2], ah[i][3], bh[jx][0], bh[jx][1]);
                }
        }
        __syncthreads();
        if (t + 1 < nt) {
            stage_store(Ah + (1 - c) * ABUF, Al + (1 - c) * ABUF,
                        Bh + (1 - c) * BBUF, Bl + (1 - c) * BBUF,
                        arow, akq, brow, bkq, ra0, ra1, rb0);
            __syncthreads();
        }
    }
}

__device__ void gemm_tile(float* __restrict__ C, int N, const float* __restrict__ bias,
                          int accum,
                          const float* A0, const float* B0, int K0, int l0,
                          const float* A1, const float* B1, int K1, int l1,
                          int m0, int n0, int tid, uint32_t* sm_u) {
    uint32_t* Ah = sm_u;
    uint32_t* Bh = Ah + 2 * ABUF;
    uint32_t* Al = Bh + 2 * BBUF;
    uint32_t* Bl = Al + 2 * ABUF;
    float acc[2][4][4];
#pragma unroll
    for (int i = 0; i < 2; ++i)
#pragma unroll
        for (int jx = 0; jx < 4; ++jx)
#pragma unroll
            for (int q = 0; q < 4; ++q) acc[i][jx][q] = 0.f;

    gemm_part(A0, B0, K0, l0, m0, n0, tid, Ah, Al, Bh, Bl, acc);
    if (A1) gemm_part(A1, B1, K1, l1, m0, n0, tid, Ah, Al, Bh, Bl, acc);

    const int lane = tid & 31, warp = tid >> 5;
    const int wm = warp >> 1, wn = warp & 1, g = lane >> 2, tg = lane & 3;
#pragma unroll
    for (int i = 0; i < 2; ++i)
#pragma unroll
        for (int jx = 0; jx < 4; ++jx) {
            int r = m0 + wm * 32 + i * 16 + g;
            int cc = n0 + wn * 32 + jx * 8 + 2 * tg;
            float2 bb = make_float2(0.f, 0.f);
            if (bias) bb = *(const float2*)&bias[cc];
            float2* p0 = (float2*)&C[(size_t)r * N + cc];
            float2* p1 = (float2*)&C[(size_t)(r + 8) * N + cc];
            float2 v0 = make_float2(acc[i][jx][0] + bb.x, acc[i][jx][1] + bb.y);
            float2 v1 = make_float2(acc[i][jx][2] + bb.x, acc[i][jx][3] + bb.y);
            if (accum) {
                float2 o0 = *p0, o1 = *p1;
                v0.x += o0.x; v0.y += o0.y; v1.x += o1.x; v1.y += o1.y;
            }
            *p0 = v0;
            *p1 = v1;
        }
}

// =====================================================================
// MEGA KERNEL v7: R14 GJ + restructured epilogue (z/yD in idle window)
// =====================================================================
__global__ void __launch_bounds__(256, 2) mega_kernel(
    const float* __restrict__ u, const float* __restrict__ x0,
    const float* __restrict__ C1, const float* __restrict__ D11,
    const float* __restrict__ D12, const float* __restrict__ lam,
    const float* __restrict__ Fm, const float* __restrict__ B1,
    const float* __restrict__ B2, const float* __restrict__ E,
    const float* __restrict__ C2, const float* __restrict__ D22,
    float* __restrict__ yout) {
    extern __shared__ float smf[];
    __shared__ int s_tile;
    const int b = blockIdx.x;
    const int tid = threadIdx.x;
    int phase = 0;

    if (b >= BAT_BLOCKS) {
        // ================= GJ GROUP (120 blocks) =================
        const int g = b - BAT_BLOCKS;
        float* Ds = smf;
        float* RP = Ds + 64 * 65;
        float* Fs = RP + 64 * 65;
        float* rowbuf = Fs + 64 * 65;
        float* colbuf = rowbuf + 128;
        const int tr = tid >> 4, tc = tid & 15;

        // --- transposed init: WLU = [E^T | C2^T] ---
        {
            float* tsh = smf;
            const int tx = tid & 31, ty = tid >> 5;
            for (int tu = g; tu < 512; tu += GJ_BLOCKS) {
                const int R0 = (tu & 15) * 32;
                const int Cc0 = (tu >> 4) * 32;
                const float* src = (Cc0 < 512) ? (E + (size_t)Cc0 * 512 + R0)
                                               : (C2 + (size_t)(Cc0 - 512) * 512 + R0);
                __syncthreads();
#pragma unroll
                for (int i = 0; i < 32; i += 8)
                    tsh[(ty + i) * 33 + tx] = src[(size_t)(ty + i) * 512 + tx];
                __syncthreads();
#pragma unroll
                for (int i = 0; i < 32; i += 8)
                    g_WLU[(size_t)(R0 + ty + i) * 1024 + Cc0 + tx] = tsh[tx * 33 + ty + i];
            }
        }
        gbar(&g_bar_gj, GJ_BLOCKS, phase, tid);

        // --- bootstrap: block 0 inverts pivot(0) ---
        if (g == 0) {
            invert_from_gwlu(0, tid, rowbuf, colbuf, &g_Dinvg[0][0]);
            __threadfence();
            if (tid == 0) g_dgen = 0;
        }

        // --- 8 GJ steps (R14 designated-inverter structure) ---
        for (int kb = 0; kb < 8; ++kb) {
            const int pc = kb * 64;
            const int ntiles = 15 - kb;
            const int tile = g >> 3, chunk = g & 7;
            const bool active = (tile < ntiles);
            const bool desig = (tile == 0) && (chunk == kb + 1) && (kb < 7);

            if (active) {
                if (tid == 0) {
                    while (g_dgen < kb) __nanosleep(64);
                }
                __syncthreads();
                __threadfence();
                const float* dsrc = &g_Dinvg[kb & 1][0];
                for (int idx = tid; idx < 4096; idx += 256)
                    Ds[(idx >> 6) * 65 + (idx & 63)] = dsrc[idx];

                const int c0 = pc + 64 + tile * 64;
                for (int idx = tid; idx < 4096; idx += 256) {
                    int k = idx >> 6, cx = idx & 63;
                    Fs[k * 65 + cx] = g_WLU[(size_t)(pc + k) * 1024 + c0 + cx];
                }
                __syncthreads();

                float rp[4][4] = {};
                for (int k = 0; k < 64; ++k) {
                    float w0 = Fs[k * 65 + tc * 4 + 0];
                    float w1 = Fs[k * 65 + tc * 4 + 1];
                    float w2 = Fs[k * 65 + tc * 4 + 2];
                    float w3 = Fs[k * 65 + tc * 4 + 3];
#pragma unroll
                    for (int i = 0; i < 4; ++i) {
                        float d = Ds[(tr * 4 + i) * 65 + k];
                        rp[i][0] += d * w0; rp[i][1] += d * w1;
                        rp[i][2] += d * w2; rp[i][3] += d * w3;
                    }
                }
                __syncthreads();
#pragma unroll
                for (int i = 0; i < 4; ++i)
#pragma unroll
                    for (int jx = 0; jx < 4; ++jx)
                        RP[(tr * 4 + i) * 65 + tc * 4 + jx] = rp[i][jx];
                __syncthreads();

                if (chunk == kb) {
                    float* dst = &g_RPbuf[kb & 1][0];
                    for (int idx = tid; idx < 4096; idx += 256) {
                        int r = idx >> 6, cx = idx & 63;
                        dst[(size_t)r * 1024 + c0 + cx] = RP[r * 65 + cx];
                    }
                } else {
                    const int r0 = chunk * 64;
                    const bool prev = (kb > 0) && (chunk == kb - 1);
                    const float* pbuf = &g_RPbuf[(kb + 1) & 1][0];
                    for (int idx = tid; idx < 4096; idx += 256) {
                        int r = idx >> 6, k = idx & 63;
                        Fs[r * 65 + k] = prev ? pbuf[(size_t)r * 1024 + pc + k]
                                              : g_WLU[(size_t)(r0 + r) * 1024 + pc + k];
                    }
                    __syncthreads();
                    float acc[4][4] = {};
                    for (int k = 0; k < 64; ++k) {
                        float w0 = RP[k * 65 + tc * 4 + 0];
                        float w1 = RP[k * 65 + tc * 4 + 1];
                        float w2 = RP[k * 65 + tc * 4 + 2];
                        float w3 = RP[k * 65 + tc * 4 + 3];
#pragma unroll
                        for (int i = 0; i < 4; ++i) {
                            float f = Fs[(tr * 4 + i) * 65 + k];
                            acc[i][0] += f * w0; acc[i][1] += f * w1;
                            acc[i][2] += f * w2; acc[i][3] += f * w3;
                        }
                    }
                    float nv[4][4];
#pragma unroll
                    for (int i = 0; i < 4; ++i) {
                        const size_t off = (size_t)(r0 + tr * 4 + i) * 1024 + c0 + tc * 4;
                        float4 o = prev ? *(const float4*)&pbuf[(size_t)(tr * 4 + i) * 1024 + c0 + tc * 4]
                                        : *(const float4*)&g_WLU[off];
                        o.x -= acc[i][0]; o.y -= acc[i][1];
                        o.z -= acc[i][2]; o.w -= acc[i][3];
                        nv[i][0] = o.x; nv[i][1] = o.y; nv[i][2] = o.z; nv[i][3] = o.w;
                        *(float4*)&g_WLU[off] = o;
                    }
                    if (desig) {
                        __syncthreads();
#pragma unroll
                        for (int i = 0; i < 4; ++i)
#pragma unroll
                            for (int jx = 0; jx < 4; ++jx)
                                Fs[(tr * 4 + i) * 65 + tc * 4 + jx] = nv[i][jx];
                        __syncthreads();
                        invert_from_sh(Fs, tid, rowbuf, colbuf,
                                       &g_Dinvg[(kb + 1) & 1][0]);
                        __threadfence();
                        if (tid == 0) g_dgen = kb + 1;
                    }
                }
            }
            gbar(&g_bar_gj, GJ_BLOCKS, phase, tid);
        }

        // --- final commit of chunk-7 pivot rows (cols 512..1024) ---
        {
            const float* src = &g_RPbuf[1][0];
            for (int t = g * 256 + tid; t < 8192; t += GJ_BLOCKS * 256) {
                int r = t >> 7, c4 = (t & 127) * 4;
                *(float4*)&g_WLU[(size_t)(448 + r) * 1024 + 512 + c4] =
                    *(const float4*)&src[(size_t)r * 1024 + 512 + c4];
            }
        }
        gbar(&g_bar_gj, GJ_BLOCKS, phase, tid);

        // --- transpose G (=M^T, ld 1024) -> Mc (M row-major, ld 512) ---
        {
            float* tsh = smf;  // 32x33
            const int tx = tid & 31, ty = tid >> 5;
            for (int tu = g; tu < 256; tu += GJ_BLOCKS) {
                const int k0 = (tu & 15) * 32;   // G row (k)
                const int n0 = (tu >> 4) * 32;   // G col (n)
                __syncthreads();
#pragma unroll
                for (int i = 0; i < 32; i += 8)
                    tsh[(ty + i) * 33 + tx] =
                        g_WLU[(size_t)(k0 + ty + i) * 1024 + 512 + n0 + tx];
                __syncthreads();
#pragma unroll
                for (int i = 0; i < 32; i += 8)
                    g_Mc[(size_t)(n0 + ty + i) * 512 + k0 + tx] = tsh[tx * 33 + ty + i];
            }
        }
        gbar(&g_bar_gj, GJ_BLOCKS, phase, tid);
        if (g == 0 && tid == 0) {
            __threadfence();
            atomicExch((int*)&g_done, 1);
        }

        wait_flag(&g_batdone, tid);
    } else {
        // ================= BATCH GROUP (168 blocks) =================
        const int v = b;

        // --- prep: D11T (64 tiles) + c1x0 + fx0 ---
        if (v < 67) {
            if (v < 64) {
                float* tsh = smf;
                const int bx = (v & 7) * 32, by = (v >> 3) * 32;
                const int tx = tid & 31, ty = tid >> 5;
#pragma unroll
                for (int i = 0; i < 32; i += 8)
                    tsh[(ty + i) * 33 + tx] = D11[(size_t)(by + ty + i) * 256 + bx + tx];
                __syncthreads();
#pragma unroll
                for (int i = 0; i < 32; i += 8)
                    g_D11T[(size_t)(bx + ty + i) * 256 + by + tx] = tsh[tx * 33 + ty + i];
            } else {
                const float4* xv = (const float4*)x0;
                if (v == 64) {
                    int n = tid;
                    const float4* r = (const float4*)(C1 + (size_t)n * DIN);
                    float s = 0.f;
                    for (int k = 0; k < DIN / 4; ++k) {
                        float4 a = r[k], bb = xv[k];
                        s += a.x * bb.x + a.y * bb.y + a.z * bb.z + a.w * bb.w;
                    }
                    g_c1x0[n] = s;
                } else {
                    int n = (v - 65) * 256 + tid;
                    const float4* r = (const float4*)(Fm + (size_t)n * DINT);
                    float s = 0.f;
                    for (int k = 0; k < DINT / 4; ++k) {
                        float4 a = r[k], bb = xv[k];
                        s += a.x * bb.x + a.y * bb.y + a.z * bb.z + a.w * bb.w;
                    }
                    g_fx0[n] = s;
                }
            }
        }
        gbar(&g_bar_bat, BAT_BLOCKS, phase, tid);

        // --- a = u @ D12^T + c1x0 (64 tiles) ---
        if (v < 64) {
            gemm_tile(g_a, 256, g_c1x0, 0,
                      u, D12, 512, 512,
                      nullptr, nullptr, 0, 0,
                      (v >> 2) * 128, (v & 3) * 64, tid, (uint32_t*)smf);
        }
        gbar(&g_bar_bat, BAT_BLOCKS, phase, tid);

        // --- recurrence ---
        for (int ru = v; ru < 256; ru += BAT_BLOCKS) {
            const int lane = tid & 31;
            const int rb = ru * 8 + (tid >> 5);
            const float* arow = g_a + (size_t)rb * 256;
            float acc[8], linv[8], wv[8];
#pragma unroll
            for (int q = 0; q < 8; ++q) {
                acc[q] = arow[q * 32 + lane];
                linv[q] = 1.0f / lam[q * 32 + lane];
            }
#pragma unroll
            for (int q = 0; q < 8; ++q) {
#pragma unroll 8
                for (int t = 0; t < 32; ++t) {
                    int s = q * 32 + t;
                    float scaled = acc[q] * linv[q];
                    float vx = __shfl_sync(0xffffffffu, scaled, t);
                    float wt = tanhf(vx);
                    if (lane == t) wv[q] = wt;
                    const float* col = g_D11T + (size_t)s * 256;
                    if (lane > t) acc[q] += col[q * 32 + lane] * wt;
#pragma unroll
                    for (int q2 = q + 1; q2 < 8; ++q2)
                        acc[q2] += col[q2 * 32 + lane] * wt;
                }
            }
#pragma unroll
            for (int q = 0; q < 8; ++q)
                g_wm[(size_t)rb * 256 + q * 32 + lane] = wv[q];
        }
        gbar(&g_bar_bat, BAT_BLOCKS, phase, tid);

        // --- z = x0@F^T + w@B1^T + u@B2^T  (bias fx0; 128 tiles) ---
        if (v < 128) {
            gemm_tile(g_z, 512, g_fx0, 0,
                      g_wm, B1, 256, 256,
                      u, B2, 512, 512,
                      (v >> 3) * 128, (v & 7) * 64, tid, (uint32_t*)smf);
        }
        gbar(&g_bar_bat, BAT_BLOCKS, phase, tid);

        // --- yD = u @ D22^T into yout (128 tiles) ---
        if (v < 128) {
            gemm_tile(yout, 512, nullptr, 0,
                      u, D22, 512, 512,
                      nullptr, nullptr, 0, 0,
                      (v >> 3) * 128, (v & 7) * 64, tid, (uint32_t*)smf);
        }
        gbar(&g_bar_bat, BAT_BLOCKS, phase, tid);
        if (v == 0 && tid == 0) {
            __threadfence();
            atomicExch((int*)&g_batdone, 1);
        }

        wait_flag(&g_done, tid);
    }

    // ============ final: yout += z @ Mc^T (K=512), all 288 blocks ============
    for (;;) {
        __syncthreads();
        if (tid == 0) s_tile = atomicAdd(&g_yctr, 1);
        __syncthreads();
        const int t = s_tile;
        if (t >= 128) break;
        gemm_tile(yout, 512, nullptr, 1,
                  g_z, g_Mc, 512, 512,
                  nullptr, nullptr, 0, 0,
                  (t >> 3) * 128, (t & 7) * 64, tid, (uint32_t*)smf);
    }
}

// ---------------- launch ----------------
extern "C" void kernel_launch(void* const* d_in, const int* in_sizes, int n_in,
                              void* d_out, int out_size) {
    const float *u, *x0, *C1, *D11, *D12, *lam, *Fm, *B1, *B2, *E, *C2, *D21, *D22;
    if (in_sizes[0] == BATCH * DIN) {
        u   = (const float*)d_in[0];  x0  = (const float*)d_in[1];
        C1  = (const float*)d_in[2];  D11 = (const float*)d_in[3];
        D12 = (const float*)d_in[4];  lam = (const float*)d_in[5];
        Fm  = (const float*)d_in[6];  B1  = (const float*)d_in[7];
        B2  = (const float*)d_in[8];  E   = (const float*)d_in[9];
        C2  = (const float*)d_in[10]; D21 = (const float*)d_in[11];
        D22 = (const float*)d_in[12];
    } else {
        C1  = (const float*)d_in[0];  D11 = (const float*)d_in[1];
        D12 = (const float*)d_in[2];  lam = (const float*)d_in[3];
        Fm  = (const float*)d_in[4];  B1  = (const float*)d_in[5];
        B2  = (const float*)d_in[6];  E   = (const float*)d_in[7];
        C2  = (const float*)d_in[8];  D21 = (const float*)d_in[9];
        D22 = (const float*)d_in[10]; u   = (const float*)d_in[11];
        x0  = (const float*)d_in[12];
    }
    (void)D21;  // identically zero by construction

    cudaFuncSetAttribute(mega_kernel,
                         cudaFuncAttributeMaxDynamicSharedMemorySize, GEMM_SMEM);

    reset_kernel<<<1, 32>>>();
    mega_kernel<<<TOT_BLOCKS, 256, GEMM_SMEM>>>(
        u, x0, C1, D11, D12, lam, Fm, B1, B2, E, C2, D22, (float*)d_out);
}

// round 17
// speedup vs baseline: 1.1826x; 1.0238x over previous
#include <cuda_runtime.h>
#include <math.h>
#include <stdint.h>

#define BATCH 2048
#define DIN   512
#define DOUT  512
#define DINT  512
#define DNL   256

#define BAT_BLOCKS  168
#define GJ_BLOCKS   120
#define TOT_BLOCKS  288

#define GEMM_SMEM ((2 * (128 * 20) + 2 * (64 * 20)) * 8)  // 61440

// ---------------- device scratch ----------------
__device__ __align__(16) float g_WLU[512 * 1024];
__device__ __align__(16) float g_RPbuf[2][64 * 1024];
__device__ __align__(16) float g_Dinvg[2][64 * 64];
__device__ __align__(16) float g_a[BATCH * DNL];
__device__ __align__(16) float g_wm[BATCH * DNL];
__device__ __align__(16) float g_z[BATCH * DINT];
__device__ __align__(16) float g_Mc[DOUT * DINT];
__device__ __align__(16) float g_D11T[DNL * DNL];
__device__ __align__(16) float g_c1x0[DNL];
__device__ __align__(16) float g_fx0[DINT];
__device__ volatile int g_bar_gj;
__device__ volatile int g_bar_bat;
__device__ volatile int g_done;
__device__ volatile int g_batdone;
__device__ volatile int g_dgen;
__device__ int g_yctr;

__global__ void reset_kernel() {
    g_bar_gj = 0; g_bar_bat = 0; g_done = 0; g_batdone = 0;
    g_dgen = -1; g_yctr = 0;
}

// ---------------- sync helpers ----------------
__device__ __forceinline__ void gbar(volatile int* ctr, int nblocks, int& phase, int tid) {
    __syncthreads();
    ++phase;
    if (tid == 0) {
        __threadfence();
        atomicAdd((int*)ctr, 1);
        const int target = nblocks * phase;
        while (*ctr < target) __nanosleep(64);
        __threadfence();
    }
    __syncthreads();
}

__device__ __forceinline__ void wait_flag(volatile int* flag, int tid) {
    if (tid == 0) {
        while (*flag == 0) __nanosleep(128);
        __threadfence();
    }
    __syncthreads();
}

// ---------------- tf32 helpers ----------------
__device__ __forceinline__ uint32_t f2tf(float f) {
    uint32_t u;
    asm("cvt.rna.tf32.f32 %0, %1;" : "=r"(u) : "f"(f));
    return u;
}
__device__ __forceinline__ void mma8(float& c0, float& c1, float& c2, float& c3,
                                     uint32_t a0, uint32_t a1, uint32_t a2, uint32_t a3,
                                     uint32_t b0, uint32_t b1) {
    asm volatile(
        "mma.sync.aligned.m16n8k8.row.col.f32.tf32.tf32.f32 "
        "{%0,%1,%2,%3},{%4,%5,%6,%7},{%8,%9},{%0,%1,%2,%3};"
        : "+f"(c0), "+f"(c1), "+f"(c2), "+f"(c3)
        : "r"(a0), "r"(a1), "r"(a2), "r"(a3), "r"(b0), "r"(b1));
}

// ---------------- warp-fragment 64x64x64 matmul (3x split, exact-ish) ----------
// C = A @ B; A, B in smem with row stride 65. Warp w: rows (w>>1)*16..+16,
// cols (w&1)*32..+32 as 4 n-frags. acc[nf][0..3] per PTX m16n8k8 layout.
__device__ __forceinline__ void mm64(const float* __restrict__ A,
                                     const float* __restrict__ B,
                                     int warp, int lane, float (&acc)[4][4]) {
    const int m0 = (warp >> 1) * 16, n0 = (warp & 1) * 32;
    const int g = lane >> 2, tg = lane & 3;
#pragma unroll
    for (int ks = 0; ks < 8; ++ks) {
        const int k0 = ks * 8;
        float af0 = A[(m0 + g) * 65 + k0 + tg];
        float af1 = A[(m0 + 8 + g) * 65 + k0 + tg];
        float af2 = A[(m0 + g) * 65 + k0 + tg + 4];
        float af3 = A[(m0 + 8 + g) * 65 + k0 + tg + 4];
        uint32_t ah0 = f2tf(af0), ah1 = f2tf(af1), ah2 = f2tf(af2), ah3 = f2tf(af3);
        uint32_t al0 = f2tf(af0 - __uint_as_float(ah0));
        uint32_t al1 = f2tf(af1 - __uint_as_float(ah1));
        uint32_t al2 = f2tf(af2 - __uint_as_float(ah2));
        uint32_t al3 = f2tf(af3 - __uint_as_float(ah3));
#pragma unroll
        for (int nf = 0; nf < 4; ++nf) {
            const int n = n0 + nf * 8 + g;
            float b0f = B[(k0 + tg) * 65 + n];
            float b1f = B[(k0 + tg + 4) * 65 + n];
            uint32_t bh0 = f2tf(b0f), bh1 = f2tf(b1f);
            uint32_t bl0 = f2tf(b0f - __uint_as_float(bh0));
            uint32_t bl1 = f2tf(b1f - __uint_as_float(bh1));
            mma8(acc[nf][0], acc[nf][1], acc[nf][2], acc[nf][3],
                 al0, al1, al2, al3, bh0, bh1);
            mma8(acc[nf][0], acc[nf][1], acc[nf][2], acc[nf][3],
                 ah0, ah1, ah2, ah3, bl0, bl1);
            mma8(acc[nf][0], acc[nf][1], acc[nf][2], acc[nf][3],
                 ah0, ah1, ah2, ah3, bh0, bh1);
        }
    }
}

// ---------------- fully-unrolled 64x64 GJ inversion core ----------------
__device__ __forceinline__ void gj_inv_core(int tid, float v[4][8],
                                            float* rowbuf, float* colbuf,
                                            float* __restrict__ outg) {
    const int rg = tid >> 4, cg = tid & 15;
#pragma unroll 64
    for (int jj = 0; jj < 64; ++jj) {
        const int pr = jj >> 2, sub = jj & 3;
        const int pcg = jj >> 3, subc = jj & 7;
        if (rg == pr) {
#pragma unroll
            for (int q = 0; q < 8; ++q) rowbuf[cg * 8 + q] = v[sub][q];
        }
        if (cg == pcg) {
#pragma unroll
            for (int i = 0; i < 4; ++i) colbuf[rg * 4 + i] = v[i][subc];
        }
        __syncthreads();
        const float pinv = 1.0f / rowbuf[jj];
        float f[4];
#pragma unroll
        for (int i = 0; i < 4; ++i) f[i] = colbuf[rg * 4 + i] * pinv;
        float rv[8];
#pragma unroll
        for (int q = 0; q < 8; ++q) rv[q] = rowbuf[cg * 8 + q];
        if (rg == pr) {
#pragma unroll
            for (int q = 0; q < 8; ++q) v[sub][q] = rv[q] * pinv;
        }
#pragma unroll
        for (int i = 0; i < 4; ++i) {
            if (rg == pr && i == sub) continue;
#pragma unroll
            for (int q = 0; q < 8; ++q) v[i][q] -= f[i] * rv[q];
        }
        __syncthreads();
    }
#pragma unroll
    for (int i = 0; i < 4; ++i) {
        int r = (tid >> 4) * 4 + i;
#pragma unroll
        for (int jx = 0; jx < 8; ++jx) {
            int cx = (tid & 15) * 8 + jx;
            if (cx >= 64) outg[r * 64 + (cx - 64)] = v[i][jx];
        }
    }
    __syncthreads();
}

__device__ __forceinline__ void invert_from_gwlu(int pc, int tid,
                                                 float* rowbuf, float* colbuf,
                                                 float* outg) {
    const int rg = tid >> 4, cg = tid & 15;
    float v[4][8];
#pragma unroll
    for (int i = 0; i < 4; ++i) {
        int r = rg * 4 + i;
#pragma unroll
        for (int jx = 0; jx < 8; ++jx) {
            int cx = cg * 8 + jx;
            v[i][jx] = (cx < 64) ? g_WLU[(size_t)(pc + r) * 1024 + pc + cx]
                                 : ((cx - 64) == r ? 1.f : 0.f);
        }
    }
    gj_inv_core(tid, v, rowbuf, colbuf, outg);
}

__device__ __forceinline__ void invert_from_sh(const float* Ts, int tid,
                                               float* rowbuf, float* colbuf,
                                               float* outg) {
    const int rg = tid >> 4, cg = tid & 15;
    float v[4][8];
#pragma unroll
    for (int i = 0; i < 4; ++i) {
        int r = rg * 4 + i;
#pragma unroll
        for (int jx = 0; jx < 8; ++jx) {
            int cx = cg * 8 + jx;
            v[i][jx] = (cx < 64) ? Ts[r * 65 + cx] : ((cx - 64) == r ? 1.f : 0.f);
        }
    }
    gj_inv_core(tid, v, rowbuf, colbuf, outg);
}

// ---------------- batch GEMM machinery (SPLIT runtime flag) ----------------
#define ASTRIDE 20
#define ABUF (128 * ASTRIDE)
#define BBUF (64 * ASTRIDE)

__device__ __forceinline__ void stage_store(uint32_t* Ah, uint32_t* Al,
                                            uint32_t* Bh, uint32_t* Bl, int split,
                                            int arow, int akq, int brow, int bkq,
                                            float4 ra0, float4 ra1, float4 rb0) {
    uint32_t* ah = Ah + arow * ASTRIDE + akq;
    uint32_t* al = Al + arow * ASTRIDE + akq;
    float av[8] = {ra0.x, ra0.y, ra0.z, ra0.w, ra1.x, ra1.y, ra1.z, ra1.w};
#pragma unroll
    for (int jx = 0; jx < 8; ++jx) {
        uint32_t h = f2tf(av[jx]);
        ah[jx] = h;
        if (split) al[jx] = f2tf(av[jx] - __uint_as_float(h));
    }
    uint32_t* bh = Bh + brow * ASTRIDE + bkq;
    uint32_t* bl = Bl + brow * ASTRIDE + bkq;
    float bv[4] = {rb0.x, rb0.y, rb0.z, rb0.w};
#pragma unroll
    for (int jx = 0; jx < 4; ++jx) {
        uint32_t h = f2tf(bv[jx]);
        bh[jx] = h;
        if (split) bl[jx] = f2tf(bv[jx] - __uint_as_float(h));
    }
}

__device__ void gemm_part(const float* __restrict__ A,
                          const float* __restrict__ Bm,
                          int K, int ldb, int m0, int n0, int tid, int split,
                          uint32_t* Ah, uint32_t* Al,
                          uint32_t* Bh, uint32_t* Bl,
                          float (&acc)[2][4][4]) {
    const int arow = tid >> 1, akq = (tid & 1) * 8;
    const int brow = tid >> 2, bkq = (tid & 3) * 4;
    const int lane = tid & 31, warp = tid >> 5;
    const int wm = warp >> 1, wn = warp & 1, g = lane >> 2, tg = lane & 3;
    const int nt = K >> 4;
    float4 ra0, ra1, rb0;
    {
        const float* ap = A + (size_t)(m0 + arow) * K + akq;
        ra0 = *(const float4*)ap;
        ra1 = *(const float4*)(ap + 4);
        const float* bp = Bm + (size_t)(n0 + brow) * ldb + bkq;
        rb0 = *(const float4*)bp;
    }
    __syncthreads();
    stage_store(Ah, Al, Bh, Bl, split, arow, akq, brow, bkq, ra0, ra1, rb0);
    __syncthreads();
    for (int t = 0; t < nt; ++t) {
        const int c = t & 1;
        if (t + 1 < nt) {
            const float* ap = A + (size_t)(m0 + arow) * K + (t + 1) * 16 + akq;
            ra0 = *(const float4*)ap;
            ra1 = *(const float4*)(ap + 4);
            const float* bp = Bm + (size_t)(n0 + brow) * ldb + (t + 1) * 16 + bkq;
            rb0 = *(const float4*)bp;
        }
        const uint32_t* Abh = Ah + c * ABUF;
        const uint32_t* Abl = Al + c * ABUF;
        const uint32_t* Bbh = Bh + c * BBUF;
        const uint32_t* Bbl = Bl + c * BBUF;
#pragma unroll
        for (int ks = 0; ks < 16; ks += 8) {
            uint32_t ah[2][4], al[2][4], bh[4][2], bl[4][2];
#pragma unroll
            for (int i = 0; i < 2; ++i) {
                int r = (wm * 32 + i * 16 + g) * ASTRIDE + ks + tg;
                ah[i][0] = Abh[r];
                ah[i][1] = Abh[r + 8 * ASTRIDE];
                ah[i][2] = Abh[r + 4];
                ah[i][3] = Abh[r + 8 * ASTRIDE + 4];
                if (split) {
                    al[i][0] = Abl[r];
                    al[i][1] = Abl[r + 8 * ASTRIDE];
                    al[i][2] = Abl[r + 4];
                    al[i][3] = Abl[r + 8 * ASTRIDE + 4];
                }
            }
#pragma unroll
            for (int jx = 0; jx < 4; ++jx) {
                int r = (wn * 32 + jx * 8 + g) * ASTRIDE + ks + tg;
                bh[jx][0] = Bbh[r];     bh[jx][1] = Bbh[r + 4];
                if (split) { bl[jx][0] = Bbl[r]; bl[jx][1] = Bbl[r + 4]; }
            }
#pragma unroll
            for (int i = 0; i < 2; ++i)
#pragma unroll
                for (int jx = 0; jx < 4; ++jx) {
                    if (split) {
                        mma8(acc[i][jx][0], acc[i][jx][1], acc[i][jx][2], acc[i][jx][3],
                             al[i][0], al[i][1], al[i][2], al[i][3], bh[jx][0], bh[jx][1]);
                        mma8(acc[i][jx][0], acc[i][jx][1], acc[i][jx][2], acc[i][jx][3],
                             ah[i][0], ah[i][1], ah[i][2], ah[i][3], bl[jx][0], bl[jx][1]);
                    }
                    mma8(acc[i][jx][0], acc[i][jx][1], acc[i][jx][2], acc[i][jx][3],
                         ah[i][0], ah[i][1], ah[i][2], ah[i][3], bh[jx][0], bh[jx][1]);
                }
        }
        __syncthreads();
        if (t + 1 < nt) {
            stage_store(Ah + (1 - c) * ABUF, Al + (1 - c) * ABUF,
                        Bh + (1 - c) * BBUF, Bl + (1 - c) * BBUF, split,
                        arow, akq, brow, bkq, ra0, ra1, rb0);
            __syncthreads();
        }
    }
}

__device__ void gemm_tile(float* __restrict__ C, int N, const float* __restrict__ bias,
                          int accum, int split,
                          const float* A0, const float* B0, int K0, int l0,
                          const float* A1, const float* B1, int K1, int l1,
                          int m0, int n0, int tid, uint32_t* sm_u) {
    uint32_t* Ah = sm_u;
    uint32_t* Bh = Ah + 2 * ABUF;
    uint32_t* Al = Bh + 2 * BBUF;
    uint32_t* Bl = Al + 2 * ABUF;
    float acc[2][4][4];
#pragma unroll
    for (int i = 0; i < 2; ++i)
#pragma unroll
        for (int jx = 0; jx < 4; ++jx)
#pragma unroll
            for (int q = 0; q < 4; ++q) acc[i][jx][q] = 0.f;

    gemm_part(A0, B0, K0, l0, m0, n0, tid, split, Ah, Al, Bh, Bl, acc);
    if (A1) gemm_part(A1, B1, K1, l1, m0, n0, tid, split, Ah, Al, Bh, Bl, acc);

    const int lane = tid & 31, warp = tid >> 5;
    const int wm = warp >> 1, wn = warp & 1, g = lane >> 2, tg = lane & 3;
#pragma unroll
    for (int i = 0; i < 2; ++i)
#pragma unroll
        for (int jx = 0; jx < 4; ++jx) {
            int r = m0 + wm * 32 + i * 16 + g;
            int cc = n0 + wn * 32 + jx * 8 + 2 * tg;
            float2 bb = make_float2(0.f, 0.f);
            if (bias) bb = *(const float2*)&bias[cc];
            float2* p0 = (float2*)&C[(size_t)r * N + cc];
            float2* p1 = (float2*)&C[(size_t)(r + 8) * N + cc];
            float2 v0 = make_float2(acc[i][jx][0] + bb.x, acc[i][jx][1] + bb.y);
            float2 v1 = make_float2(acc[i][jx][2] + bb.x, acc[i][jx][3] + bb.y);
            if (accum) {
                float2 o0 = *p0, o1 = *p1;
                v0.x += o0.x; v0.y += o0.y; v1.x += o1.x; v1.y += o1.y;
            }
            *p0 = v0;
            *p1 = v1;
        }
}

// =====================================================================
// MEGA KERNEL v8: GJ matmuls on tensor cores; single-pass yD/final
// =====================================================================
__global__ void __launch_bounds__(256, 2) mega_kernel(
    const float* __restrict__ u, const float* __restrict__ x0,
    const float* __restrict__ C1, const float* __restrict__ D11,
    const float* __restrict__ D12, const float* __restrict__ lam,
    const float* __restrict__ Fm, const float* __restrict__ B1,
    const float* __restrict__ B2, const float* __restrict__ E,
    const float* __restrict__ C2, const float* __restrict__ D22,
    float* __restrict__ yout) {
    extern __shared__ float smf[];
    __shared__ int s_tile;
    const int b = blockIdx.x;
    const int tid = threadIdx.x;
    const int lane = tid & 31, warp = tid >> 5;
    int phase = 0;

    if (b >= BAT_BLOCKS) {
        // ================= GJ GROUP (120 blocks) =================
        const int g = b - BAT_BLOCKS;
        float* Ds = smf;
        float* RP = Ds + 64 * 65;
        float* Fs = RP + 64 * 65;
        float* rowbuf = Fs + 64 * 65;
        float* colbuf = rowbuf + 128;
        const int fm0 = (warp >> 1) * 16, fn0 = (warp & 1) * 32;
        const int fg = lane >> 2, ftg = lane & 3;

        // --- transposed init: WLU = [E^T | C2^T] ---
        {
            float* tsh = smf;
            const int tx = tid & 31, ty = tid >> 5;
            for (int tu = g; tu < 512; tu += GJ_BLOCKS) {
                const int R0 = (tu & 15) * 32;
                const int Cc0 = (tu >> 4) * 32;
                const float* src = (Cc0 < 512) ? (E + (size_t)Cc0 * 512 + R0)
                                               : (C2 + (size_t)(Cc0 - 512) * 512 + R0);
                __syncthreads();
#pragma unroll
                for (int i = 0; i < 32; i += 8)
                    tsh[(ty + i) * 33 + tx] = src[(size_t)(ty + i) * 512 + tx];
                __syncthreads();
#pragma unroll
                for (int i = 0; i < 32; i += 8)
                    g_WLU[(size_t)(R0 + ty + i) * 1024 + Cc0 + tx] = tsh[tx * 33 + ty + i];
            }
        }
        gbar(&g_bar_gj, GJ_BLOCKS, phase, tid);

        if (g == 0) {
            invert_from_gwlu(0, tid, rowbuf, colbuf, &g_Dinvg[0][0]);
            __threadfence();
            if (tid == 0) g_dgen = 0;
        }

        // --- 8 GJ steps ---
        for (int kb = 0; kb < 8; ++kb) {
            const int pc = kb * 64;
            const int ntiles = 15 - kb;
            const int tile = g >> 3, chunk = g & 7;
            const bool active = (tile < ntiles);
            const bool desig = (tile == 0) && (chunk == kb + 1) && (kb < 7);

            if (active) {
                if (tid == 0) {
                    while (g_dgen < kb) __nanosleep(64);
                }
                __syncthreads();
                __threadfence();
                const float* dsrc = &g_Dinvg[kb & 1][0];
                for (int idx = tid; idx < 4096; idx += 256)
                    Ds[(idx >> 6) * 65 + (idx & 63)] = dsrc[idx];

                const int c0 = pc + 64 + tile * 64;
                for (int idx = tid; idx < 4096; idx += 256) {
                    int k = idx >> 6, cx = idx & 63;
                    Fs[k * 65 + cx] = g_WLU[(size_t)(pc + k) * 1024 + c0 + cx];
                }
                __syncthreads();

                // RP = Dinv @ Wk (tensor cores, 3x split)
                {
                    float acc[4][4];
#pragma unroll
                    for (int nf = 0; nf < 4; ++nf)
#pragma unroll
                        for (int q = 0; q < 4; ++q) acc[nf][q] = 0.f;
                    mm64(Ds, Fs, warp, lane, acc);
                    __syncthreads();  // all warps done reading Fs (as Wk)
#pragma unroll
                    for (int nf = 0; nf < 4; ++nf) {
                        const int cfr = fn0 + nf * 8 + 2 * ftg;
                        RP[(fm0 + fg) * 65 + cfr]     = acc[nf][0];
                        RP[(fm0 + fg) * 65 + cfr + 1] = acc[nf][1];
                        RP[(fm0 + 8 + fg) * 65 + cfr]     = acc[nf][2];
                        RP[(fm0 + 8 + fg) * 65 + cfr + 1] = acc[nf][3];
                    }
                    __syncthreads();
                }

                if (chunk == kb) {
                    float* dst = &g_RPbuf[kb & 1][0];
                    for (int idx = tid; idx < 4096; idx += 256) {
                        int r = idx >> 6, cx = idx & 63;
                        dst[(size_t)r * 1024 + c0 + cx] = RP[r * 65 + cx];
                    }
                } else {
                    const int r0 = chunk * 64;
                    const bool prev = (kb > 0) && (chunk == kb - 1);
                    const float* pbuf = &g_RPbuf[(kb + 1) & 1][0];
                    for (int idx = tid; idx < 4096; idx += 256) {
                        int r = idx >> 6, k = idx & 63;
                        Fs[r * 65 + k] = prev ? pbuf[(size_t)r * 1024 + pc + k]
                                              : g_WLU[(size_t)(r0 + r) * 1024 + pc + k];
                    }
                    __syncthreads();

                    // acc = F @ RP (tensor cores)
                    float acc[4][4];
#pragma unroll
                    for (int nf = 0; nf < 4; ++nf)
#pragma unroll
                        for (int q = 0; q < 4; ++q) acc[nf][q] = 0.f;
                    mm64(Fs, RP, warp, lane, acc);

                    // update: v = old - acc; write to g_WLU (float2 pairs)
                    float nv[4][4];
#pragma unroll
                    for (int nf = 0; nf < 4; ++nf) {
                        const int cfr = fn0 + nf * 8 + 2 * ftg;
                        const size_t o0 = (size_t)(r0 + fm0 + fg) * 1024 + c0 + cfr;
                        const size_t o1 = (size_t)(r0 + fm0 + 8 + fg) * 1024 + c0 + cfr;
                        float2 w0, w1;
                        if (prev) {
                            w0 = *(const float2*)&pbuf[(size_t)(fm0 + fg) * 1024 + c0 + cfr];
                            w1 = *(const float2*)&pbuf[(size_t)(fm0 + 8 + fg) * 1024 + c0 + cfr];
                        } else {
                            w0 = *(const float2*)&g_WLU[o0];
                            w1 = *(const float2*)&g_WLU[o1];
                        }
                        w0.x -= acc[nf][0]; w0.y -= acc[nf][1];
                        w1.x -= acc[nf][2]; w1.y -= acc[nf][3];
                        nv[nf][0] = w0.x; nv[nf][1] = w0.y;
                        nv[nf][2] = w1.x; nv[nf][3] = w1.y;
                        *(float2*)&g_WLU[o0] = w0;
                        *(float2*)&g_WLU[o1] = w1;
                    }
                    if (desig) {
                        __syncthreads();  // all warps done reading Fs
#pragma unroll
                        for (int nf = 0; nf < 4; ++nf) {
                            const int cfr = fn0 + nf * 8 + 2 * ftg;
                            Fs[(fm0 + fg) * 65 + cfr]     = nv[nf][0];
                            Fs[(fm0 + fg) * 65 + cfr + 1] = nv[nf][1];
                            Fs[(fm0 + 8 + fg) * 65 + cfr]     = nv[nf][2];
                            Fs[(fm0 + 8 + fg) * 65 + cfr + 1] = nv[nf][3];
                        }
                        __syncthreads();
                        invert_from_sh(Fs, tid, rowbuf, colbuf,
                                       &g_Dinvg[(kb + 1) & 1][0]);
                        __threadfence();
                        if (tid == 0) g_dgen = kb + 1;
                    }
                }
            }
            gbar(&g_bar_gj, GJ_BLOCKS, phase, tid);
        }

        // --- final commit of chunk-7 pivot rows (cols 512..1024) ---
        {
            const float* src = &g_RPbuf[1][0];
            for (int t = g * 256 + tid; t < 8192; t += GJ_BLOCKS * 256) {
                int r = t >> 7, c4 = (t & 127) * 4;
                *(float4*)&g_WLU[(size_t)(448 + r) * 1024 + 512 + c4] =
                    *(const float4*)&src[(size_t)r * 1024 + 512 + c4];
            }
        }
        gbar(&g_bar_gj, GJ_BLOCKS, phase, tid);

        // --- transpose G -> Mc (M row-major, ld 512) ---
        {
            float* tsh = smf;
            const int tx = tid & 31, ty = tid >> 5;
            for (int tu = g; tu < 256; tu += GJ_BLOCKS) {
                const int k0 = (tu & 15) * 32;
                const int n0 = (tu >> 4) * 32;
                __syncthreads();
#pragma unroll
                for (int i = 0; i < 32; i += 8)
                    tsh[(ty + i) * 33 + tx] =
                        g_WLU[(size_t)(k0 + ty + i) * 1024 + 512 + n0 + tx];
                __syncthreads();
#pragma unroll
                for (int i = 0; i < 32; i += 8)
                    g_Mc[(size_t)(n0 + ty + i) * 512 + k0 + tx] = tsh[tx * 33 + ty + i];
            }
        }
        gbar(&g_bar_gj, GJ_BLOCKS, phase, tid);
        if (g == 0 && tid == 0) {
            __threadfence();
            atomicExch((int*)&g_done, 1);
        }

        wait_flag(&g_batdone, tid);
    } else {
        // ================= BATCH GROUP (168 blocks) =================
        const int v = b;

        if (v < 67) {
            if (v < 64) {
                float* tsh = smf;
                const int bx = (v & 7) * 32, by = (v >> 3) * 32;
                const int tx = tid & 31, ty = tid >> 5;
#pragma unroll
                for (int i = 0; i < 32; i += 8)
                    tsh[(ty + i) * 33 + tx] = D11[(size_t)(by + ty + i) * 256 + bx + tx];
                __syncthreads();
#pragma unroll
                for (int i = 0; i < 32; i += 8)
                    g_D11T[(size_t)(bx + ty + i) * 256 + by + tx] = tsh[tx * 33 + ty + i];
            } else {
                const float4* xv = (const float4*)x0;
                if (v == 64) {
                    int n = tid;
                    const float4* r = (const float4*)(C1 + (size_t)n * DIN);
                    float s = 0.f;
                    for (int k = 0; k < DIN / 4; ++k) {
                        float4 a = r[k], bb = xv[k];
                        s += a.x * bb.x + a.y * bb.y + a.z * bb.z + a.w * bb.w;
                    }
                    g_c1x0[n] = s;
                } else {
                    int n = (v - 65) * 256 + tid;
                    const float4* r = (const float4*)(Fm + (size_t)n * DINT);
                    float s = 0.f;
                    for (int k = 0; k < DINT / 4; ++k) {
                        float4 a = r[k], bb = xv[k];
                        s += a.x * bb.x + a.y * bb.y + a.z * bb.z + a.w * bb.w;
                    }
                    g_fx0[n] = s;
                }
            }
        }
        gbar(&g_bar_bat, BAT_BLOCKS, phase, tid);

        if (v < 64) {
            gemm_tile(g_a, 256, g_c1x0, 0, 1,
                      u, D12, 512, 512,
                      nullptr, nullptr, 0, 0,
                      (v >> 2) * 128, (v & 3) * 64, tid, (uint32_t*)smf);
        }
        gbar(&g_bar_bat, BAT_BLOCKS, phase, tid);

        for (int ru = v; ru < 256; ru += BAT_BLOCKS) {
            const int rb = ru * 8 + warp;
            const float* arow = g_a + (size_t)rb * 256;
            float acc[8], linv[8], wv[8];
#pragma unroll
            for (int q = 0; q < 8; ++q) {
                acc[q] = arow[q * 32 + lane];
                linv[q] = 1.0f / lam[q * 32 + lane];
            }
#pragma unroll
            for (int q = 0; q < 8; ++q) {
#pragma unroll 8
                for (int t = 0; t < 32; ++t) {
                    int s = q * 32 + t;
                    float scaled = acc[q] * linv[q];
                    float vx = __shfl_sync(0xffffffffu, scaled, t);
                    float wt = tanhf(vx);
                    if (lane == t) wv[q] = wt;
                    const float* col = g_D11T + (size_t)s * 256;
                    if (lane > t) acc[q] += col[q * 32 + lane] * wt;
#pragma unroll
                    for (int q2 = q + 1; q2 < 8; ++q2)
                        acc[q2] += col[q2 * 32 + lane] * wt;
                }
            }
#pragma unroll
            for (int q = 0; q < 8; ++q)
                g_wm[(size_t)rb * 256 + q * 32 + lane] = wv[q];
        }
        gbar(&g_bar_bat, BAT_BLOCKS, phase, tid);

        // z = x0@F^T + w@B1^T + u@B2^T (3x split: feeds final)
        if (v < 128) {
            gemm_tile(g_z, 512, g_fx0, 0, 1,
                      g_wm, B1, 256, 256,
                      u, B2, 512, 512,
                      (v >> 3) * 128, (v & 7) * 64, tid, (uint32_t*)smf);
        }
        gbar(&g_bar_bat, BAT_BLOCKS, phase, tid);

        // yD = u @ D22^T (single-pass tf32)
        if (v < 128) {
            gemm_tile(yout, 512, nullptr, 0, 0,
                      u, D22, 512, 512,
                      nullptr, nullptr, 0, 0,
                      (v >> 3) * 128, (v & 7) * 64, tid, (uint32_t*)smf);
        }
        gbar(&g_bar_bat, BAT_BLOCKS, phase, tid);
        if (v == 0 && tid == 0) {
            __threadfence();
            atomicExch((int*)&g_batdone, 1);
        }

        wait_flag(&g_done, tid);
    }

    // ============ final: yout += z @ Mc^T (single-pass tf32) ============
    for (;;) {
        __syncthreads();
        if (tid == 0) s_tile = atomicAdd(&g_yctr, 1);
        __syncthreads();
        const int t = s_tile;
        if (t >= 128) break;
        gemm_tile(yout, 512, nullptr, 1, 0,
                  g_z, g_Mc, 512, 512,
                  nullptr, nullptr, 0, 0,
                  (t >> 3) * 128, (t & 7) * 64, tid, (uint32_t*)smf);
    }
}

// ---------------- launch ----------------
extern "C" void kernel_launch(void* const* d_in, const int* in_sizes, int n_in,
                              void* d_out, int out_size) {
    const float *u, *x0, *C1, *D11, *D12, *lam, *Fm, *B1, *B2, *E, *C2, *D21, *D22;
    if (in_sizes[0] == BATCH * DIN) {
        u   = (const float*)d_in[0];  x0  = (const float*)d_in[1];
        C1  = (const float*)d_in[2];  D11 = (const float*)d_in[3];
        D12 = (const float*)d_in[4];  lam = (const float*)d_in[5];
        Fm  = (const float*)d_in[6];  B1  = (const float*)d_in[7];
        B2  = (const float*)d_in[8];  E   = (const float*)d_in[9];
        C2  = (const float*)d_in[10]; D21 = (const float*)d_in[11];
        D22 = (const float*)d_in[12];
    } else {
        C1  = (const float*)d_in[0];  D11 = (const float*)d_in[1];
        D12 = (const float*)d_in[2];  lam = (const float*)d_in[3];
        Fm  = (const float*)d_in[4];  B1  = (const float*)d_in[5];
        B2  = (const float*)d_in[6];  E   = (const float*)d_in[7];
        C2  = (const float*)d_in[8];  D21 = (const float*)d_in[9];
        D22 = (const float*)d_in[10]; u   = (const float*)d_in[11];
        x0  = (const float*)d_in[12];
    }
    (void)D21;  // identically zero by construction

    cudaFuncSetAttribute(mega_kernel,
                         cudaFuncAttributeMaxDynamicSharedMemorySize, GEMM_SMEM);

    reset_kernel<<<1, 32>>>();
    mega_kernel<<<TOT_BLOCKS, 256, GEMM_SMEM>>>(
        u, x0, C1, D11, D12, lam, Fm, B1, B2, E, C2, D22, (float*)d_out);
}